// round 7
// baseline (speedup 1.0000x reference)
#include <cuda_runtime.h>
#include <cuda_bf16.h>
#include <math_constants.h>
#include <cstdint>

// ---------------- problem constants ----------------
#define BB   16
#define TT   2048
#define INC  80
#define HC   512
#define DC   512
#define KC   1024
#define RR   (BB*TT)          // 32768 rows

// ---------------- scratch ----------------
__device__ float g_bufA[(size_t)RR * DC];
__device__ float g_bufB[(size_t)RR * DC];
__device__ float g_wt[3*INC*HC + 3*HC*DC];            // fp32 enc weights
__device__ __align__(16) __nv_bfloat16 g_whi[983040]; // dec weights hi
__device__ __align__(16) __nv_bfloat16 g_wlo[983040]; // dec weights lo
__device__ float g_cbT[DC * KC];
__device__ float g_cnorm[KC];
__device__ int   g_idx[RR];

#define WT_OFF_E1 0                         // [240, 512]
#define WT_OFF_E2 (WT_OFF_E1 + 3*INC*HC)    // [1536, 512]
// bf16 regions, layout [KPAD][COUTP]
#define WO_D1 0               // [1536][512]
#define WO_D2 786432          // [1536][128]

// ---------------- PTX helpers ---------------------------------------------
__device__ __forceinline__ uint32_t smem_u32(const void* p) {
    uint32_t a;
    asm("{ .reg .u64 t; cvta.to.shared.u64 t, %1; cvt.u32.u64 %0, t; }"
        : "=r"(a) : "l"(p));
    return a;
}
__device__ __forceinline__ void ldsm_x4(uint32_t* r, uint32_t addr) {
    asm volatile("ldmatrix.sync.aligned.m8n8.x4.shared.b16 {%0,%1,%2,%3}, [%4];"
                 : "=r"(r[0]), "=r"(r[1]), "=r"(r[2]), "=r"(r[3]) : "r"(addr));
}
__device__ __forceinline__ void ldsm_x4t(uint32_t* r, uint32_t addr) {
    asm volatile("ldmatrix.sync.aligned.m8n8.x4.trans.shared.b16 {%0,%1,%2,%3}, [%4];"
                 : "=r"(r[0]), "=r"(r[1]), "=r"(r[2]), "=r"(r[3]) : "r"(addr));
}
__device__ __forceinline__ void mma16816(float* c, const uint32_t* a,
                                         const uint32_t* b) {
    asm volatile(
        "mma.sync.aligned.m16n8k16.row.col.f32.bf16.bf16.f32 "
        "{%0,%1,%2,%3}, {%4,%5,%6,%7}, {%8,%9}, {%0,%1,%2,%3};"
        : "+f"(c[0]), "+f"(c[1]), "+f"(c[2]), "+f"(c[3])
        : "r"(a[0]), "r"(a[1]), "r"(a[2]), "r"(a[3]), "r"(b[0]), "r"(b[1]));
}
#define STS128(a, r0, r1, r2, r3) \
    asm volatile("st.shared.v4.b32 [%0], {%1,%2,%3,%4};" \
                 :: "r"(a), "r"(r0), "r"(r1), "r"(r2), "r"(r3) : "memory")

__device__ __forceinline__ uint32_t pack2bf(float a, float b) {
    __nv_bfloat162 h = __floats2bfloat162_rn(a, b);
    return *reinterpret_cast<uint32_t*>(&h);
}

// f32x2 packed FMA (FFMA2): d = a*b + d, two independent fp32 lanes (exact)
__device__ __forceinline__ void fma2(unsigned long long& d, unsigned long long a,
                                     unsigned long long b) {
    asm("fma.rn.f32x2 %0, %1, %2, %0;" : "+l"(d) : "l"(a), "l"(b));
}
__device__ __forceinline__ unsigned long long dup2(float a) {
    unsigned long long r;
    asm("mov.b64 %0, {%1,%1};" : "=l"(r) : "f"(a));
    return r;
}
__device__ __forceinline__ void unpack2(unsigned long long v, float& lo, float& hi) {
    asm("mov.b64 {%0,%1}, %2;" : "=f"(lo), "=f"(hi) : "l"(v));
}

// ---------------- prep kernels --------------------------------------------
__global__ void k_wtransform(const float* __restrict__ w, float* __restrict__ wt,
                             int Cin, int Cout) {
    int n = 3 * Cin * Cout;
    for (int i = blockIdx.x * blockDim.x + threadIdx.x; i < n;
         i += gridDim.x * blockDim.x) {
        int k  = i / Cout;
        int co = i - k * Cout;
        int dt = k / Cin;
        int ci = k - dt * Cin;
        wt[i] = w[(co * Cin + ci) * 3 + dt];
    }
}
__global__ void k_wprep(const float* __restrict__ w, __nv_bfloat16* __restrict__ hi,
                        __nv_bfloat16* __restrict__ lo,
                        int Cin, int Cout, int CinP, int CoutP) {
    int kpad = 3 * CinP;
    int n = kpad * CoutP;
    for (int i = blockIdx.x * blockDim.x + threadIdx.x; i < n;
         i += gridDim.x * blockDim.x) {
        int kp = i / CoutP;
        int nn = i - kp * CoutP;
        int dt = kp / CinP;
        int ci = kp - dt * CinP;
        float v = (nn < Cout && ci < Cin) ? w[(nn * Cin + ci) * 3 + dt] : 0.f;
        __nv_bfloat16 h = __float2bfloat16_rn(v);
        hi[i] = h;
        lo[i] = __float2bfloat16_rn(v - __bfloat162float(h));
    }
}
__global__ void k_cbT(const float* __restrict__ cb) {
    int n = DC * KC;
    for (int i = blockIdx.x * blockDim.x + threadIdx.x; i < n;
         i += gridDim.x * blockDim.x) {
        int d = i >> 10;
        int k = i & (KC - 1);
        g_cbT[i] = cb[k * DC + d];
    }
}
__global__ void k_cnorm(const float* __restrict__ cb) {
    int k = blockIdx.x;
    float s = 0.f;
    for (int d = threadIdx.x; d < DC; d += 256) {
        float v = cb[k * DC + d];
        s += v * v;
    }
    __shared__ float red[256];
    red[threadIdx.x] = s;
    __syncthreads();
    for (int o = 128; o > 0; o >>= 1) {
        if (threadIdx.x < o) red[threadIdx.x] += red[threadIdx.x + o];
        __syncthreads();
    }
    if (threadIdx.x == 0) g_cnorm[k] = red[0];
}

// ---------------- fp32 conv GEMM (encoder; FFMA2 packed) -------------------
template<int CIN, int COUT, bool RELU>
__global__ __launch_bounds__(256)
void k_convgemm(const float* __restrict__ A, const float* __restrict__ W,
                const float* __restrict__ bias, float* __restrict__ C) {
    constexpr int BM = 128, BN = 128, BK = 16, KEFF = 3 * CIN;
    __shared__ float As[2][BK][BM];
    __shared__ float Bs[2][BK][BN];

    const int tid = threadIdx.x;
    const int tx = tid & 15, ty = tid >> 4;
    const int rowBase = blockIdx.y * BM;
    const int colBase = blockIdx.x * BN;

    const int ar0 = tid >> 2, ak0 = (tid & 3) << 2;
    const int ar1 = ar0 + 64;
    const int r0 = rowBase + ar0, r1 = rowBase + ar1;
    const int t0 = r0 & (TT - 1), t1 = r1 & (TT - 1);
    const bool f0 = (t0 == 0), l0 = (t0 == TT - 1);
    const bool f1 = (t1 == 0), l1 = (t1 == TT - 1);

    const int br0 = tid >> 5;
    const int bc0 = (tid & 31) << 2;
    const int co0 = colBase + bc0;

    float4 ra0, ra1, rb0, rb1;

    auto fetch = [&](int k0) {
        const int dt = k0 / CIN;
        const int ci = k0 - dt * CIN + ak0;
        const bool z0 = (dt == 0 && f0) || (dt == 2 && l0);
        const bool z1 = (dt == 0 && f1) || (dt == 2 && l1);
        const float* p0 = A + (size_t)(r0 + dt - 1) * CIN + ci;
        const float* p1 = A + (size_t)(r1 + dt - 1) * CIN + ci;
        ra0 = z0 ? make_float4(0.f, 0.f, 0.f, 0.f) : *(const float4*)p0;
        ra1 = z1 ? make_float4(0.f, 0.f, 0.f, 0.f) : *(const float4*)p1;
        rb0 = *(const float4*)(W + (size_t)(k0 + br0) * COUT + co0);
        rb1 = *(const float4*)(W + (size_t)(k0 + br0 + 8) * COUT + co0);
    };
    auto stage = [&](int buf) {
        As[buf][ak0 + 0][ar0] = ra0.x; As[buf][ak0 + 1][ar0] = ra0.y;
        As[buf][ak0 + 2][ar0] = ra0.z; As[buf][ak0 + 3][ar0] = ra0.w;
        As[buf][ak0 + 0][ar1] = ra1.x; As[buf][ak0 + 1][ar1] = ra1.y;
        As[buf][ak0 + 2][ar1] = ra1.z; As[buf][ak0 + 3][ar1] = ra1.w;
        *(float4*)&Bs[buf][br0][bc0]     = rb0;
        *(float4*)&Bs[buf][br0 + 8][bc0] = rb1;
    };

    unsigned long long acc[8][4] = {};   // [row i][col pair jp]; 0ull == (0f,0f)

    auto compute = [&](int buf) {
#pragma unroll
        for (int k = 0; k < BK; k++) {
            float a[8];
            unsigned long long b2[4];
            *(float4*)(a)     = *(const float4*)&As[buf][k][ty * 8];
            *(float4*)(a + 4) = *(const float4*)&As[buf][k][ty * 8 + 4];
            *(ulonglong2*)(b2)     = *(const ulonglong2*)&Bs[buf][k][tx * 8];
            *(ulonglong2*)(b2 + 2) = *(const ulonglong2*)&Bs[buf][k][tx * 8 + 4];
#pragma unroll
            for (int i = 0; i < 8; i++) {
                const unsigned long long a2 = dup2(a[i]);
#pragma unroll
                for (int jp = 0; jp < 4; jp++) fma2(acc[i][jp], a2, b2[jp]);
            }
        }
    };

    fetch(0);
    stage(0);
    __syncthreads();
    int buf = 0;
    for (int k0 = BK; k0 < KEFF; k0 += BK) {
        fetch(k0);
        compute(buf);
        stage(buf ^ 1);
        __syncthreads();
        buf ^= 1;
    }
    compute(buf);

#pragma unroll
    for (int i = 0; i < 8; i++) {
        const int r = rowBase + ty * 8 + i;
#pragma unroll
        for (int h4 = 0; h4 < 2; h4++) {        // two float4 stores
            const int co = colBase + tx * 8 + h4 * 4;
            float4 v;
            unpack2(acc[i][h4 * 2 + 0], v.x, v.y);
            unpack2(acc[i][h4 * 2 + 1], v.z, v.w);
            v.x += bias[co + 0]; v.y += bias[co + 1];
            v.z += bias[co + 2]; v.w += bias[co + 3];
            if (RELU) {
                v.x = fmaxf(v.x, 0.f); v.y = fmaxf(v.y, 0.f);
                v.z = fmaxf(v.z, 0.f); v.w = fmaxf(v.w, 0.f);
            }
            *(float4*)(C + (size_t)r * COUT + co) = v;
        }
    }
}

// ---------------- decoder conv GEMM via mma.sync bf16 hi/lo split ----------
template<int CIN, int CINP, int COUTP, int COUT, bool RELU, bool GATHER>
__global__ __launch_bounds__(256, 1)
void k_conv_mma(const float* __restrict__ A, const __nv_bfloat16* __restrict__ Whi,
                const __nv_bfloat16* __restrict__ Wlo, const float* __restrict__ bias,
                float* __restrict__ C) {
    constexpr int KPAD = 3 * CINP;
    constexpr int NCHUNK = KPAD / 32;
    constexpr int APITCH = 40;
    constexpr int BPITCH = 136;
    constexpr int ASZ = 128 * APITCH * 2;
    constexpr int BSZ = 32 * BPITCH * 2;

    extern __shared__ __align__(16) char smem[];
    const uint32_t sb = smem_u32(smem);
    const uint32_t oAH = sb, oAL = sb + 2 * ASZ;
    const uint32_t oBH = sb + 4 * ASZ, oBL = sb + 4 * ASZ + 2 * BSZ;

    const int tid = threadIdx.x;
    const int wid = tid >> 5, lane = tid & 31;
    const int mwarp = wid >> 2, nwarp = wid & 3;
    const int rowBase = blockIdx.y * 128;
    const int colBase = blockIdx.x * 128;

    const int ar = tid >> 1, half = tid & 1;
    const int r = rowBase + ar;
    const int tloc = r & (TT - 1);
    int gi[3];
    if (GATHER) {
#pragma unroll
        for (int dt = 0; dt < 3; dt++) {
            int rr = r + dt - 1;
            rr = rr < 0 ? 0 : (rr >= RR ? RR - 1 : rr);
            gi[dt] = g_idx[rr];
        }
    }
    const int bk = tid >> 3, seg = tid & 7;

    float4 va[4];
    uint4  wh[2], wl[2];

    auto fetch = [&](int c) {
        const int dt = (c * 32) / CINP;
        const int ci0 = c * 32 - dt * CINP;
        const bool ztap = (dt == 0 && tloc == 0) || (dt == 2 && tloc == TT - 1);
        const float* src;
        if (GATHER) {
            src = A + (size_t)gi[dt] * CIN;
        } else {
            src = A + (size_t)(r + dt - 1) * CIN;
        }
#pragma unroll
        for (int j = 0; j < 4; j++) {
            const int ci = ci0 + half * 16 + j * 4;
            const bool ok = !ztap && (CIN == CINP || ci < CIN);
            va[j] = ok ? *(const float4*)(src + ci) : make_float4(0.f, 0.f, 0.f, 0.f);
        }
        const size_t g = (size_t)(c * 32 + bk) * COUTP + colBase + seg * 16;
        wh[0] = *(const uint4*)(Whi + g);
        wh[1] = *(const uint4*)(Whi + g + 8);
        wl[0] = *(const uint4*)(Wlo + g);
        wl[1] = *(const uint4*)(Wlo + g + 8);
    };

    auto stage = [&](int buf) {
        float e[16];
        *(float4*)(e)      = va[0]; *(float4*)(e + 4)  = va[1];
        *(float4*)(e + 8)  = va[2]; *(float4*)(e + 12) = va[3];
        uint32_t hp[8], lp[8];
#pragma unroll
        for (int q = 0; q < 8; q++) {
            float h0 = __bfloat162float(__float2bfloat16_rn(e[2 * q]));
            float h1 = __bfloat162float(__float2bfloat16_rn(e[2 * q + 1]));
            hp[q] = pack2bf(h0, h1);
            lp[q] = pack2bf(e[2 * q] - h0, e[2 * q + 1] - h1);
        }
        const uint32_t aoff = (uint32_t)(ar * APITCH + half * 16) * 2 + buf * ASZ;
        STS128(oAH + aoff,      hp[0], hp[1], hp[2], hp[3]);
        STS128(oAH + aoff + 16, hp[4], hp[5], hp[6], hp[7]);
        STS128(oAL + aoff,      lp[0], lp[1], lp[2], lp[3]);
        STS128(oAL + aoff + 16, lp[4], lp[5], lp[6], lp[7]);
        const uint32_t boff = (uint32_t)(bk * BPITCH + seg * 16) * 2 + buf * BSZ;
        STS128(oBH + boff,      wh[0].x, wh[0].y, wh[0].z, wh[0].w);
        STS128(oBH + boff + 16, wh[1].x, wh[1].y, wh[1].z, wh[1].w);
        STS128(oBL + boff,      wl[0].x, wl[0].y, wl[0].z, wl[0].w);
        STS128(oBL + boff + 16, wl[1].x, wl[1].y, wl[1].z, wl[1].w);
    };

    float acc[4][4][4] = {};

    const uint32_t a_row = (lane & 15);
    const uint32_t a_k8  = (lane >> 4) * 8;
    const uint32_t b_k   = (lane & 15);
    const uint32_t b_n8  = (lane >> 4) * 8;

    auto compute = [&](int buf) {
        const uint32_t aH = oAH + buf * ASZ, aL = oAL + buf * ASZ;
        const uint32_t bH = oBH + buf * BSZ, bL = oBL + buf * BSZ;
#pragma unroll
        for (int ks = 0; ks < 2; ks++) {
            uint32_t AH[4][4], AL[4][4], BH[2][4], BL[2][4];
#pragma unroll
            for (int mt = 0; mt < 4; mt++) {
                const uint32_t ao =
                    ((mwarp * 64 + mt * 16 + a_row) * APITCH + ks * 16 + a_k8) * 2;
                ldsm_x4(AH[mt], aH + ao);
                ldsm_x4(AL[mt], aL + ao);
            }
#pragma unroll
            for (int pr = 0; pr < 2; pr++) {
                const uint32_t bo =
                    ((b_k + ks * 16) * BPITCH + nwarp * 32 + pr * 16 + b_n8) * 2;
                ldsm_x4t(BH[pr], bH + bo);
                ldsm_x4t(BL[pr], bL + bo);
            }
#pragma unroll
            for (int mt = 0; mt < 4; mt++)
#pragma unroll
                for (int nt = 0; nt < 4; nt++) {
                    const int pr = nt >> 1, hf = nt & 1;
                    mma16816(acc[mt][nt], AH[mt], &BH[pr][hf * 2]);
                    mma16816(acc[mt][nt], AL[mt], &BH[pr][hf * 2]);
                    mma16816(acc[mt][nt], AH[mt], &BL[pr][hf * 2]);
                }
        }
    };

    fetch(0);
    stage(0);
    __syncthreads();
    int buf = 0;
    for (int c = 1; c < NCHUNK; c++) {
        fetch(c);
        compute(buf);
        stage(buf ^ 1);
        __syncthreads();
        buf ^= 1;
    }
    compute(buf);

#pragma unroll
    for (int mt = 0; mt < 4; mt++) {
#pragma unroll
        for (int nt = 0; nt < 4; nt++) {
            const int col = colBase + nwarp * 32 + nt * 8 + (lane & 3) * 2;
            if ((COUT % 128) != 0 && col >= COUT) continue;
            const float b0 = bias[col], b1 = bias[col + 1];
            const int r0 = rowBase + mwarp * 64 + mt * 16 + (lane >> 2);
#pragma unroll
            for (int hh = 0; hh < 2; hh++) {
                float2 o;
                o.x = acc[mt][nt][hh * 2 + 0] + b0;
                o.y = acc[mt][nt][hh * 2 + 1] + b1;
                if (RELU) { o.x = fmaxf(o.x, 0.f); o.y = fmaxf(o.y, 0.f); }
                *(float2*)(C + (size_t)(r0 + hh * 8) * COUT + col) = o;
            }
        }
    }
}

// ---------------- VQ: fused scores GEMM + argmin (exact fp32, FFMA2) -------
__global__ __launch_bounds__(256)
void k_vq(const float* __restrict__ Z, float* __restrict__ idxOutF) {
    constexpr int BM = 128, BN = 128, BK = 16;
    constexpr int KTILES = DC / BK;
    constexpr int NITER = (KC / BN) * KTILES;
    __shared__ float As[2][BK][BM];
    __shared__ float Bs[2][BK][BN];
    __shared__ float sval[128][17];
    __shared__ int   sidx[128][17];

    const int tid = threadIdx.x;
    const int tx = tid & 15, ty = tid >> 4;
    const int rowBase = blockIdx.x * BM;
    const int ar0 = tid >> 2, ak0 = (tid & 3) << 2;
    const int ar1 = ar0 + 64;
    const int br0 = tid >> 5;
    const int bc0 = (tid & 31) << 2;
    const float* arow0 = Z + (size_t)(rowBase + ar0) * DC + ak0;
    const float* arow1 = Z + (size_t)(rowBase + ar1) * DC + ak0;

    float4 ra0, ra1, rb0, rb1;

    auto fetch = [&](int iter) {
        const int nb = (iter >> 5) << 7;
        const int d0 = (iter & 31) << 4;
        ra0 = *(const float4*)(arow0 + d0);
        ra1 = *(const float4*)(arow1 + d0);
        rb0 = *(const float4*)(g_cbT + (size_t)(d0 + br0) * KC + nb + bc0);
        rb1 = *(const float4*)(g_cbT + (size_t)(d0 + br0 + 8) * KC + nb + bc0);
    };
    auto stage = [&](int buf) {
        As[buf][ak0 + 0][ar0] = ra0.x; As[buf][ak0 + 1][ar0] = ra0.y;
        As[buf][ak0 + 2][ar0] = ra0.z; As[buf][ak0 + 3][ar0] = ra0.w;
        As[buf][ak0 + 0][ar1] = ra1.x; As[buf][ak0 + 1][ar1] = ra1.y;
        As[buf][ak0 + 2][ar1] = ra1.z; As[buf][ak0 + 3][ar1] = ra1.w;
        *(float4*)&Bs[buf][br0][bc0]     = rb0;
        *(float4*)&Bs[buf][br0 + 8][bc0] = rb1;
    };

    unsigned long long acc[8][4];
    float minv[8];
    int   mini[8];
#pragma unroll
    for (int i = 0; i < 8; i++) { minv[i] = CUDART_INF_F; mini[i] = 0; }

    auto compute = [&](int buf) {
#pragma unroll
        for (int k = 0; k < BK; k++) {
            float a[8];
            unsigned long long b2[4];
            *(float4*)(a)     = *(const float4*)&As[buf][k][ty * 8];
            *(float4*)(a + 4) = *(const float4*)&As[buf][k][ty * 8 + 4];
            *(ulonglong2*)(b2)     = *(const ulonglong2*)&Bs[buf][k][tx * 8];
            *(ulonglong2*)(b2 + 2) = *(const ulonglong2*)&Bs[buf][k][tx * 8 + 4];
#pragma unroll
            for (int i = 0; i < 8; i++) {
                const unsigned long long a2 = dup2(a[i]);
#pragma unroll
                for (int jp = 0; jp < 4; jp++) fma2(acc[i][jp], a2, b2[jp]);
            }
        }
    };

    fetch(0);
    stage(0);
    __syncthreads();
    int buf = 0;
    for (int iter = 0; iter < NITER; iter++) {
        if ((iter & (KTILES - 1)) == 0) {
#pragma unroll
            for (int i = 0; i < 8; i++)
#pragma unroll
                for (int jp = 0; jp < 4; jp++) acc[i][jp] = 0ull;
        }
        const bool more = (iter + 1 < NITER);
        if (more) fetch(iter + 1);
        compute(buf);
        if ((iter & (KTILES - 1)) == KTILES - 1) {
            // running argmin update (ascending k -> first-min wins on strict <)
            const int nb = (iter >> 5) << 7;
#pragma unroll
            for (int jp = 0; jp < 4; jp++) {
                const int kk0 = nb + tx * 8 + jp * 2;
                const float cn0 = g_cnorm[kk0];
                const float cn1 = g_cnorm[kk0 + 1];
#pragma unroll
                for (int i = 0; i < 8; i++) {
                    float d0, d1;
                    unpack2(acc[i][jp], d0, d1);
                    float s0 = fmaf(-2.f, d0, cn0);
                    float s1 = fmaf(-2.f, d1, cn1);
                    if (s0 < minv[i]) { minv[i] = s0; mini[i] = kk0; }
                    if (s1 < minv[i]) { minv[i] = s1; mini[i] = kk0 + 1; }
                }
            }
        }
        if (more) {
            stage(buf ^ 1);
            __syncthreads();
            buf ^= 1;
        }
    }

#pragma unroll
    for (int i = 0; i < 8; i++) {
        sval[ty * 8 + i][tx] = minv[i];
        sidx[ty * 8 + i][tx] = mini[i];
    }
    __syncthreads();
    if (tid < 128) {
        float bv = sval[tid][0];
        int   bi = sidx[tid][0];
#pragma unroll
        for (int x = 1; x < 16; x++) {
            float v = sval[tid][x];
            int   ii = sidx[tid][x];
            if (v < bv || (v == bv && ii < bi)) { bv = v; bi = ii; }
        }
        g_idx[rowBase + tid] = bi;
        if (idxOutF) idxOutF[rowBase + tid] = (float)bi;
    }
}

// ---------------- launch ---------------------------------------------------
extern "C" void kernel_launch(void* const* d_in, const int* in_sizes, int n_in,
                              void* d_out, int out_size) {
    const float* mels   = (const float*)d_in[0];
    const float* enc_w1 = (const float*)d_in[1];
    const float* enc_b1 = (const float*)d_in[2];
    const float* enc_w2 = (const float*)d_in[3];
    const float* enc_b2 = (const float*)d_in[4];
    const float* cb     = (const float*)d_in[5];
    const float* dec_w1 = (const float*)d_in[6];
    const float* dec_b1 = (const float*)d_in[7];
    const float* dec_w2 = (const float*)d_in[8];
    const float* dec_b2 = (const float*)d_in[9];

    float *bufA, *bufB, *wt;
    __nv_bfloat16 *whi, *wlo;
    cudaGetSymbolAddress((void**)&bufA, g_bufA);
    cudaGetSymbolAddress((void**)&bufB, g_bufB);
    cudaGetSymbolAddress((void**)&wt,   g_wt);
    cudaGetSymbolAddress((void**)&whi,  g_whi);
    cudaGetSymbolAddress((void**)&wlo,  g_wlo);

    float* out = (float*)d_out;
    float* idxOutF = (out_size >= RR * INC + RR) ? (out + (size_t)RR * INC) : nullptr;

    // prep
    k_wtransform<<<256, 256>>>(enc_w1, wt + WT_OFF_E1, INC, HC);
    k_wtransform<<<512, 256>>>(enc_w2, wt + WT_OFF_E2, HC, DC);
    k_wprep<<<512, 256>>>(dec_w1, whi + WO_D1, wlo + WO_D1, DC, HC, 512, 512);
    k_wprep<<<256, 256>>>(dec_w2, whi + WO_D2, wlo + WO_D2, HC, INC, 512, 128);
    k_cbT<<<512, 256>>>(cb);
    k_cnorm<<<KC, 256>>>(cb);

    constexpr int SMEM = 4 * (128 * 40 * 2) + 4 * (32 * 136 * 2);  // 75776 B
    cudaFuncSetAttribute((const void*)k_conv_mma<DC, 512, 512, HC, true, true>,
                         cudaFuncAttributeMaxDynamicSharedMemorySize, SMEM);
    cudaFuncSetAttribute((const void*)k_conv_mma<HC, 512, 128, INC, false, false>,
                         cudaFuncAttributeMaxDynamicSharedMemorySize, SMEM);

    dim3 g512(4, RR / 128);

    // encoder (exact fp32, FFMA2-packed — protects argmin, bit-identical)
    k_convgemm<INC, HC, true ><<<g512, 256>>>(mels, wt + WT_OFF_E1, enc_b1, bufA);
    k_convgemm<HC,  DC, false><<<g512, 256>>>(bufA, wt + WT_OFF_E2, enc_b2, bufB);

    // VQ (exact fp32, FFMA2-packed) -> g_idx
    k_vq<<<RR / 128, 256>>>(bufB, idxOutF);

    // decoder via bf16-split tensor cores (smooth error only)
    k_conv_mma<DC, 512, 512, HC, true, true>
        <<<dim3(4, RR / 128), 256, SMEM>>>(cb, whi + WO_D1, wlo + WO_D1, dec_b1, bufA);
    k_conv_mma<HC, 512, 128, INC, false, false>
        <<<dim3(1, RR / 128), 256, SMEM>>>(bufA, whi + WO_D2, wlo + WO_D2, dec_b2, out);
}

// round 8
// speedup vs baseline: 1.9109x; 1.9109x over previous
#include <cuda_runtime.h>
#include <cuda_bf16.h>
#include <math_constants.h>
#include <cstdint>

// ---------------- problem constants ----------------
#define BB   16
#define TT   2048
#define INC  80
#define HC   512
#define DC   512
#define KC   1024
#define RR   (BB*TT)          // 32768 rows

// ---------------- scratch ----------------
__device__ float g_bufA[(size_t)RR * DC];
__device__ float g_bufB[(size_t)RR * DC];
__device__ __align__(16) __nv_bfloat16 g_whi[983040];  // dec weights hi
__device__ __align__(16) __nv_bfloat16 g_wlo[983040];  // dec weights lo
__device__ __align__(16) __nv_bfloat16 g_weh[933888];  // enc weights h
__device__ __align__(16) __nv_bfloat16 g_wem[933888];  // enc weights m
__device__ __align__(16) __nv_bfloat16 g_wel[933888];  // enc weights l
__device__ float g_cbT[DC * KC];
__device__ float g_cnorm[KC];
__device__ int   g_idx[RR];

// bf16 regions, layout [KPAD][COUTP]
#define WO_D1 0               // dec1: [1536][512]
#define WO_D2 786432          // dec2: [1536][128]
#define WE_E1 0               // enc1: [288][512]
#define WE_E2 147456          // enc2: [1536][512]

// ---------------- PTX helpers ---------------------------------------------
__device__ __forceinline__ uint32_t smem_u32(const void* p) {
    uint32_t a;
    asm("{ .reg .u64 t; cvta.to.shared.u64 t, %1; cvt.u32.u64 %0, t; }"
        : "=r"(a) : "l"(p));
    return a;
}
__device__ __forceinline__ void ldsm_x4(uint32_t* r, uint32_t addr) {
    asm volatile("ldmatrix.sync.aligned.m8n8.x4.shared.b16 {%0,%1,%2,%3}, [%4];"
                 : "=r"(r[0]), "=r"(r[1]), "=r"(r[2]), "=r"(r[3]) : "r"(addr));
}
__device__ __forceinline__ void ldsm_x4t(uint32_t* r, uint32_t addr) {
    asm volatile("ldmatrix.sync.aligned.m8n8.x4.trans.shared.b16 {%0,%1,%2,%3}, [%4];"
                 : "=r"(r[0]), "=r"(r[1]), "=r"(r[2]), "=r"(r[3]) : "r"(addr));
}
__device__ __forceinline__ void mma16816(float* c, const uint32_t* a,
                                         const uint32_t* b) {
    asm volatile(
        "mma.sync.aligned.m16n8k16.row.col.f32.bf16.bf16.f32 "
        "{%0,%1,%2,%3}, {%4,%5,%6,%7}, {%8,%9}, {%0,%1,%2,%3};"
        : "+f"(c[0]), "+f"(c[1]), "+f"(c[2]), "+f"(c[3])
        : "r"(a[0]), "r"(a[1]), "r"(a[2]), "r"(a[3]), "r"(b[0]), "r"(b[1]));
}
#define STS128(a, r0, r1, r2, r3) \
    asm volatile("st.shared.v4.b32 [%0], {%1,%2,%3,%4};" \
                 :: "r"(a), "r"(r0), "r"(r1), "r"(r2), "r"(r3) : "memory")

__device__ __forceinline__ uint32_t pack2bf(float a, float b) {
    __nv_bfloat162 h = __floats2bfloat162_rn(a, b);
    return *reinterpret_cast<uint32_t*>(&h);
}

// ---------------- prep kernels --------------------------------------------
// 2-term split (decoder): w[Cout,Cin,3] -> hi/lo [3*CinP][CoutP]
__global__ void k_wprep(const float* __restrict__ w, __nv_bfloat16* __restrict__ hi,
                        __nv_bfloat16* __restrict__ lo,
                        int Cin, int Cout, int CinP, int CoutP) {
    int kpad = 3 * CinP;
    int n = kpad * CoutP;
    for (int i = blockIdx.x * blockDim.x + threadIdx.x; i < n;
         i += gridDim.x * blockDim.x) {
        int kp = i / CoutP;
        int nn = i - kp * CoutP;
        int dt = kp / CinP;
        int ci = kp - dt * CinP;
        float v = (nn < Cout && ci < Cin) ? w[(nn * Cin + ci) * 3 + dt] : 0.f;
        __nv_bfloat16 h = __float2bfloat16_rn(v);
        hi[i] = h;
        lo[i] = __float2bfloat16_rn(v - __bfloat162float(h));
    }
}
// 3-term split (encoder): w -> h/m/l [3*CinP][CoutP]
__global__ void k_wprep3(const float* __restrict__ w, __nv_bfloat16* __restrict__ wh,
                         __nv_bfloat16* __restrict__ wm, __nv_bfloat16* __restrict__ wl,
                         int Cin, int Cout, int CinP, int CoutP) {
    int kpad = 3 * CinP;
    int n = kpad * CoutP;
    for (int i = blockIdx.x * blockDim.x + threadIdx.x; i < n;
         i += gridDim.x * blockDim.x) {
        int kp = i / CoutP;
        int nn = i - kp * CoutP;
        int dt = kp / CinP;
        int ci = kp - dt * CinP;
        float v = (nn < Cout && ci < Cin) ? w[(nn * Cin + ci) * 3 + dt] : 0.f;
        __nv_bfloat16 h = __float2bfloat16_rn(v);
        float r = v - __bfloat162float(h);
        __nv_bfloat16 m = __float2bfloat16_rn(r);
        wh[i] = h;
        wm[i] = m;
        wl[i] = __float2bfloat16_rn(r - __bfloat162float(m));
    }
}
__global__ void k_cbT(const float* __restrict__ cb) {
    int n = DC * KC;
    for (int i = blockIdx.x * blockDim.x + threadIdx.x; i < n;
         i += gridDim.x * blockDim.x) {
        int d = i >> 10;
        int k = i & (KC - 1);
        g_cbT[i] = cb[k * DC + d];
    }
}
__global__ void k_cnorm(const float* __restrict__ cb) {
    int k = blockIdx.x;
    float s = 0.f;
    for (int d = threadIdx.x; d < DC; d += 256) {
        float v = cb[k * DC + d];
        s += v * v;
    }
    __shared__ float red[256];
    red[threadIdx.x] = s;
    __syncthreads();
    for (int o = 128; o > 0; o >>= 1) {
        if (threadIdx.x < o) red[threadIdx.x] += red[threadIdx.x + o];
        __syncthreads();
    }
    if (threadIdx.x == 0) g_cnorm[k] = red[0];
}

// ---------------- conv GEMM via mma.sync, 2-term bf16 split (decoder) ------
template<int CIN, int CINP, int COUTP, int COUT, bool RELU, bool GATHER>
__global__ __launch_bounds__(256, 1)
void k_conv_mma(const float* __restrict__ A, const __nv_bfloat16* __restrict__ Whi,
                const __nv_bfloat16* __restrict__ Wlo, const float* __restrict__ bias,
                float* __restrict__ C) {
    constexpr int KPAD = 3 * CINP;
    constexpr int NCHUNK = KPAD / 32;
    constexpr int APITCH = 40;
    constexpr int BPITCH = 136;
    constexpr int ASZ = 128 * APITCH * 2;
    constexpr int BSZ = 32 * BPITCH * 2;

    extern __shared__ __align__(16) char smem[];
    const uint32_t sb = smem_u32(smem);
    const uint32_t oAH = sb, oAL = sb + 2 * ASZ;
    const uint32_t oBH = sb + 4 * ASZ, oBL = sb + 4 * ASZ + 2 * BSZ;

    const int tid = threadIdx.x;
    const int wid = tid >> 5, lane = tid & 31;
    const int mwarp = wid >> 2, nwarp = wid & 3;
    const int rowBase = blockIdx.y * 128;
    const int colBase = blockIdx.x * 128;

    const int ar = tid >> 1, half = tid & 1;
    const int r = rowBase + ar;
    const int tloc = r & (TT - 1);
    int gi[3];
    if (GATHER) {
#pragma unroll
        for (int dt = 0; dt < 3; dt++) {
            int rr = r + dt - 1;
            rr = rr < 0 ? 0 : (rr >= RR ? RR - 1 : rr);
            gi[dt] = g_idx[rr];
        }
    }
    const int bk = tid >> 3, seg = tid & 7;

    float4 va[4];
    uint4  wh[2], wl[2];

    auto fetch = [&](int c) {
        const int dt = (c * 32) / CINP;
        const int ci0 = c * 32 - dt * CINP;
        const bool ztap = (dt == 0 && tloc == 0) || (dt == 2 && tloc == TT - 1);
        const float* src;
        if (GATHER) {
            src = A + (size_t)gi[dt] * CIN;
        } else {
            src = A + (size_t)(r + dt - 1) * CIN;
        }
#pragma unroll
        for (int j = 0; j < 4; j++) {
            const int ci = ci0 + half * 16 + j * 4;
            const bool ok = !ztap && (CIN == CINP || ci < CIN);
            va[j] = ok ? *(const float4*)(src + ci) : make_float4(0.f, 0.f, 0.f, 0.f);
        }
        const size_t g = (size_t)(c * 32 + bk) * COUTP + colBase + seg * 16;
        wh[0] = *(const uint4*)(Whi + g);
        wh[1] = *(const uint4*)(Whi + g + 8);
        wl[0] = *(const uint4*)(Wlo + g);
        wl[1] = *(const uint4*)(Wlo + g + 8);
    };

    auto stage = [&](int buf) {
        float e[16];
        *(float4*)(e)      = va[0]; *(float4*)(e + 4)  = va[1];
        *(float4*)(e + 8)  = va[2]; *(float4*)(e + 12) = va[3];
        uint32_t hp[8], lp[8];
#pragma unroll
        for (int q = 0; q < 8; q++) {
            float h0 = __bfloat162float(__float2bfloat16_rn(e[2 * q]));
            float h1 = __bfloat162float(__float2bfloat16_rn(e[2 * q + 1]));
            hp[q] = pack2bf(h0, h1);
            lp[q] = pack2bf(e[2 * q] - h0, e[2 * q + 1] - h1);
        }
        const uint32_t aoff = (uint32_t)(ar * APITCH + half * 16) * 2 + buf * ASZ;
        STS128(oAH + aoff,      hp[0], hp[1], hp[2], hp[3]);
        STS128(oAH + aoff + 16, hp[4], hp[5], hp[6], hp[7]);
        STS128(oAL + aoff,      lp[0], lp[1], lp[2], lp[3]);
        STS128(oAL + aoff + 16, lp[4], lp[5], lp[6], lp[7]);
        const uint32_t boff = (uint32_t)(bk * BPITCH + seg * 16) * 2 + buf * BSZ;
        STS128(oBH + boff,      wh[0].x, wh[0].y, wh[0].z, wh[0].w);
        STS128(oBH + boff + 16, wh[1].x, wh[1].y, wh[1].z, wh[1].w);
        STS128(oBL + boff,      wl[0].x, wl[0].y, wl[0].z, wl[0].w);
        STS128(oBL + boff + 16, wl[1].x, wl[1].y, wl[1].z, wl[1].w);
    };

    float acc[4][4][4] = {};

    const uint32_t a_row = (lane & 15);
    const uint32_t a_k8  = (lane >> 4) * 8;
    const uint32_t b_k   = (lane & 15);
    const uint32_t b_n8  = (lane >> 4) * 8;

    auto compute = [&](int buf) {
        const uint32_t aH = oAH + buf * ASZ, aL = oAL + buf * ASZ;
        const uint32_t bH = oBH + buf * BSZ, bL = oBL + buf * BSZ;
#pragma unroll
        for (int ks = 0; ks < 2; ks++) {
            uint32_t AH[4][4], AL[4][4], BH[2][4], BL[2][4];
#pragma unroll
            for (int mt = 0; mt < 4; mt++) {
                const uint32_t ao =
                    ((mwarp * 64 + mt * 16 + a_row) * APITCH + ks * 16 + a_k8) * 2;
                ldsm_x4(AH[mt], aH + ao);
                ldsm_x4(AL[mt], aL + ao);
            }
#pragma unroll
            for (int pr = 0; pr < 2; pr++) {
                const uint32_t bo =
                    ((b_k + ks * 16) * BPITCH + nwarp * 32 + pr * 16 + b_n8) * 2;
                ldsm_x4t(BH[pr], bH + bo);
                ldsm_x4t(BL[pr], bL + bo);
            }
#pragma unroll
            for (int mt = 0; mt < 4; mt++)
#pragma unroll
                for (int nt = 0; nt < 4; nt++) {
                    const int pr = nt >> 1, hf = nt & 1;
                    mma16816(acc[mt][nt], AH[mt], &BH[pr][hf * 2]);
                    mma16816(acc[mt][nt], AL[mt], &BH[pr][hf * 2]);
                    mma16816(acc[mt][nt], AH[mt], &BL[pr][hf * 2]);
                }
        }
    };

    fetch(0);
    stage(0);
    __syncthreads();
    int buf = 0;
    for (int c = 1; c < NCHUNK; c++) {
        fetch(c);
        compute(buf);
        stage(buf ^ 1);
        __syncthreads();
        buf ^= 1;
    }
    compute(buf);

#pragma unroll
    for (int mt = 0; mt < 4; mt++) {
#pragma unroll
        for (int nt = 0; nt < 4; nt++) {
            const int col = colBase + nwarp * 32 + nt * 8 + (lane & 3) * 2;
            if ((COUT % 128) != 0 && col >= COUT) continue;
            const float b0 = bias[col], b1 = bias[col + 1];
            const int r0 = rowBase + mwarp * 64 + mt * 16 + (lane >> 2);
#pragma unroll
            for (int hh = 0; hh < 2; hh++) {
                float2 o;
                o.x = acc[mt][nt][hh * 2 + 0] + b0;
                o.y = acc[mt][nt][hh * 2 + 1] + b1;
                if (RELU) { o.x = fmaxf(o.x, 0.f); o.y = fmaxf(o.y, 0.f); }
                *(float2*)(C + (size_t)(r0 + hh * 8) * COUT + col) = o;
            }
        }
    }
}

// ---------------- conv GEMM via mma.sync, 3-term bf16 split (encoder) ------
// fp32-class accuracy (dropped terms ~2^-27): safe upstream of the argmin.
template<int CIN, int CINP, int COUTP, int COUT, bool RELU>
__global__ __launch_bounds__(256, 1)
void k_conv_mma3(const float* __restrict__ A, const __nv_bfloat16* __restrict__ Wh,
                 const __nv_bfloat16* __restrict__ Wm, const __nv_bfloat16* __restrict__ Wl,
                 const float* __restrict__ bias, float* __restrict__ C) {
    constexpr int KPAD = 3 * CINP;
    constexpr int NCHUNK = KPAD / 32;
    constexpr int APITCH = 40;
    constexpr int BPITCH = 136;
    constexpr int ASZ = 128 * APITCH * 2;   // 10240 B per A tile
    constexpr int BSZ = 32 * BPITCH * 2;    //  8704 B per B tile

    extern __shared__ __align__(16) char smem[];
    const uint32_t sb = smem_u32(smem);
    // layout: AH[2] AM[2] AL[2] BH[2] BM[2] BL[2]
    const uint32_t oAH = sb, oAM = sb + 2 * ASZ, oAL = sb + 4 * ASZ;
    const uint32_t oBH = sb + 6 * ASZ, oBM = oBH + 2 * BSZ, oBL = oBH + 4 * BSZ;

    const int tid = threadIdx.x;
    const int wid = tid >> 5, lane = tid & 31;
    const int mwarp = wid >> 2, nwarp = wid & 3;
    const int rowBase = blockIdx.y * 128;
    const int colBase = blockIdx.x * 128;

    const int ar = tid >> 1, half = tid & 1;
    const int r = rowBase + ar;
    const int tloc = r & (TT - 1);
    const int bk = tid >> 3, seg = tid & 7;

    float4 va[4];
    uint4  wwh[2], wwm[2], wwl[2];

    auto fetch = [&](int c) {
        const int dt = (c * 32) / CINP;
        const int ci0 = c * 32 - dt * CINP;
        const bool ztap = (dt == 0 && tloc == 0) || (dt == 2 && tloc == TT - 1);
        const float* src = A + (size_t)(r + dt - 1) * CIN;
#pragma unroll
        for (int j = 0; j < 4; j++) {
            const int ci = ci0 + half * 16 + j * 4;
            const bool ok = !ztap && (CIN == CINP || ci < CIN);
            va[j] = ok ? *(const float4*)(src + ci) : make_float4(0.f, 0.f, 0.f, 0.f);
        }
        const size_t g = (size_t)(c * 32 + bk) * COUTP + colBase + seg * 16;
        wwh[0] = *(const uint4*)(Wh + g);  wwh[1] = *(const uint4*)(Wh + g + 8);
        wwm[0] = *(const uint4*)(Wm + g);  wwm[1] = *(const uint4*)(Wm + g + 8);
        wwl[0] = *(const uint4*)(Wl + g);  wwl[1] = *(const uint4*)(Wl + g + 8);
    };

    auto stage = [&](int buf) {
        float e[16];
        *(float4*)(e)      = va[0]; *(float4*)(e + 4)  = va[1];
        *(float4*)(e + 8)  = va[2]; *(float4*)(e + 12) = va[3];
        uint32_t hp[8], mp[8], lp[8];
#pragma unroll
        for (int q = 0; q < 8; q++) {
            float x0 = e[2 * q], x1 = e[2 * q + 1];
            float h0 = __bfloat162float(__float2bfloat16_rn(x0));
            float h1 = __bfloat162float(__float2bfloat16_rn(x1));
            float r0 = x0 - h0, r1 = x1 - h1;
            float m0 = __bfloat162float(__float2bfloat16_rn(r0));
            float m1 = __bfloat162float(__float2bfloat16_rn(r1));
            hp[q] = pack2bf(h0, h1);
            mp[q] = pack2bf(m0, m1);
            lp[q] = pack2bf(r0 - m0, r1 - m1);
        }
        const uint32_t aoff = (uint32_t)(ar * APITCH + half * 16) * 2 + buf * ASZ;
        STS128(oAH + aoff,      hp[0], hp[1], hp[2], hp[3]);
        STS128(oAH + aoff + 16, hp[4], hp[5], hp[6], hp[7]);
        STS128(oAM + aoff,      mp[0], mp[1], mp[2], mp[3]);
        STS128(oAM + aoff + 16, mp[4], mp[5], mp[6], mp[7]);
        STS128(oAL + aoff,      lp[0], lp[1], lp[2], lp[3]);
        STS128(oAL + aoff + 16, lp[4], lp[5], lp[6], lp[7]);
        const uint32_t boff = (uint32_t)(bk * BPITCH + seg * 16) * 2 + buf * BSZ;
        STS128(oBH + boff,      wwh[0].x, wwh[0].y, wwh[0].z, wwh[0].w);
        STS128(oBH + boff + 16, wwh[1].x, wwh[1].y, wwh[1].z, wwh[1].w);
        STS128(oBM + boff,      wwm[0].x, wwm[0].y, wwm[0].z, wwm[0].w);
        STS128(oBM + boff + 16, wwm[1].x, wwm[1].y, wwm[1].z, wwm[1].w);
        STS128(oBL + boff,      wwl[0].x, wwl[0].y, wwl[0].z, wwl[0].w);
        STS128(oBL + boff + 16, wwl[1].x, wwl[1].y, wwl[1].z, wwl[1].w);
    };

    float acc[4][4][4] = {};

    const uint32_t a_row = (lane & 15);
    const uint32_t a_k8  = (lane >> 4) * 8;
    const uint32_t b_k   = (lane & 15);
    const uint32_t b_n8  = (lane >> 4) * 8;

    auto compute = [&](int buf) {
        const uint32_t aH = oAH + buf * ASZ, aM = oAM + buf * ASZ, aL = oAL + buf * ASZ;
        const uint32_t bH = oBH + buf * BSZ, bM = oBM + buf * BSZ, bL = oBL + buf * BSZ;
#pragma unroll
        for (int ks = 0; ks < 2; ks++) {
            uint32_t AH[4][4], AM[4][4], AL[4][4];
            uint32_t BH[2][4], BM[2][4], BL[2][4];
#pragma unroll
            for (int mt = 0; mt < 4; mt++) {
                const uint32_t ao =
                    ((mwarp * 64 + mt * 16 + a_row) * APITCH + ks * 16 + a_k8) * 2;
                ldsm_x4(AH[mt], aH + ao);
                ldsm_x4(AM[mt], aM + ao);
                ldsm_x4(AL[mt], aL + ao);
            }
#pragma unroll
            for (int pr = 0; pr < 2; pr++) {
                const uint32_t bo =
                    ((b_k + ks * 16) * BPITCH + nwarp * 32 + pr * 16 + b_n8) * 2;
                ldsm_x4t(BH[pr], bH + bo);
                ldsm_x4t(BM[pr], bM + bo);
                ldsm_x4t(BL[pr], bL + bo);
            }
#pragma unroll
            for (int mt = 0; mt < 4; mt++)
#pragma unroll
                for (int nt = 0; nt < 4; nt++) {
                    const int pr = nt >> 1, hf = nt & 1;
                    float* a = acc[mt][nt];
                    mma16816(a, AH[mt], &BH[pr][hf * 2]);   // h·h'
                    mma16816(a, AH[mt], &BM[pr][hf * 2]);   // h·m'
                    mma16816(a, AM[mt], &BH[pr][hf * 2]);   // m·h'
                    mma16816(a, AH[mt], &BL[pr][hf * 2]);   // h·l'
                    mma16816(a, AM[mt], &BM[pr][hf * 2]);   // m·m'
                    mma16816(a, AL[mt], &BH[pr][hf * 2]);   // l·h'
                }
        }
    };

    fetch(0);
    stage(0);
    __syncthreads();
    int buf = 0;
    for (int c = 1; c < NCHUNK; c++) {
        fetch(c);
        compute(buf);
        stage(buf ^ 1);
        __syncthreads();
        buf ^= 1;
    }
    compute(buf);

#pragma unroll
    for (int mt = 0; mt < 4; mt++) {
#pragma unroll
        for (int nt = 0; nt < 4; nt++) {
            const int col = colBase + nwarp * 32 + nt * 8 + (lane & 3) * 2;
            if ((COUT % 128) != 0 && col >= COUT) continue;
            const float b0 = bias[col], b1 = bias[col + 1];
            const int r0 = rowBase + mwarp * 64 + mt * 16 + (lane >> 2);
#pragma unroll
            for (int hh = 0; hh < 2; hh++) {
                float2 o;
                o.x = acc[mt][nt][hh * 2 + 0] + b0;
                o.y = acc[mt][nt][hh * 2 + 1] + b1;
                if (RELU) { o.x = fmaxf(o.x, 0.f); o.y = fmaxf(o.y, 0.f); }
                *(float2*)(C + (size_t)(r0 + hh * 8) * COUT + col) = o;
            }
        }
    }
}

// ---------------- VQ: fused scores GEMM + argmin (exact fp32) -------------
__global__ __launch_bounds__(256)
void k_vq(const float* __restrict__ Z, float* __restrict__ idxOutF) {
    constexpr int BM = 128, BN = 128, BK = 16;
    constexpr int KTILES = DC / BK;
    constexpr int NITER = (KC / BN) * KTILES;
    __shared__ float As[2][BK][BM];
    __shared__ float Bs[2][BK][BN];
    __shared__ float sval[128][17];
    __shared__ int   sidx[128][17];

    const int tid = threadIdx.x;
    const int tx = tid & 15, ty = tid >> 4;
    const int rowBase = blockIdx.x * BM;
    const int ar0 = tid >> 2, ak0 = (tid & 3) << 2;
    const int ar1 = ar0 + 64;
    const int br0 = tid >> 5;
    const int bc0 = (tid & 31) << 2;
    const float* arow0 = Z + (size_t)(rowBase + ar0) * DC + ak0;
    const float* arow1 = Z + (size_t)(rowBase + ar1) * DC + ak0;

    float4 ra0, ra1, rb0, rb1;

    auto fetch = [&](int iter) {
        const int nb = (iter >> 5) << 7;
        const int d0 = (iter & 31) << 4;
        ra0 = *(const float4*)(arow0 + d0);
        ra1 = *(const float4*)(arow1 + d0);
        rb0 = *(const float4*)(g_cbT + (size_t)(d0 + br0) * KC + nb + bc0);
        rb1 = *(const float4*)(g_cbT + (size_t)(d0 + br0 + 8) * KC + nb + bc0);
    };
    auto stage = [&](int buf) {
        As[buf][ak0 + 0][ar0] = ra0.x; As[buf][ak0 + 1][ar0] = ra0.y;
        As[buf][ak0 + 2][ar0] = ra0.z; As[buf][ak0 + 3][ar0] = ra0.w;
        As[buf][ak0 + 0][ar1] = ra1.x; As[buf][ak0 + 1][ar1] = ra1.y;
        As[buf][ak0 + 2][ar1] = ra1.z; As[buf][ak0 + 3][ar1] = ra1.w;
        *(float4*)&Bs[buf][br0][bc0]     = rb0;
        *(float4*)&Bs[buf][br0 + 8][bc0] = rb1;
    };

    float acc[8][8];
    float minv[8];
    int   mini[8];
#pragma unroll
    for (int i = 0; i < 8; i++) { minv[i] = CUDART_INF_F; mini[i] = 0; }

    auto compute = [&](int buf) {
#pragma unroll
        for (int k = 0; k < BK; k++) {
            float a[8], bmat[8];
            *(float4*)(a)        = *(const float4*)&As[buf][k][ty * 8];
            *(float4*)(a + 4)    = *(const float4*)&As[buf][k][ty * 8 + 4];
            *(float4*)(bmat)     = *(const float4*)&Bs[buf][k][tx * 8];
            *(float4*)(bmat + 4) = *(const float4*)&Bs[buf][k][tx * 8 + 4];
#pragma unroll
            for (int i = 0; i < 8; i++)
#pragma unroll
                for (int j = 0; j < 8; j++)
                    acc[i][j] = fmaf(a[i], bmat[j], acc[i][j]);
        }
    };

    fetch(0);
    stage(0);
    __syncthreads();
    int buf = 0;
    for (int iter = 0; iter < NITER; iter++) {
        if ((iter & (KTILES - 1)) == 0) {
#pragma unroll
            for (int i = 0; i < 8; i++)
#pragma unroll
                for (int j = 0; j < 8; j++) acc[i][j] = 0.f;
        }
        const bool more = (iter + 1 < NITER);
        if (more) fetch(iter + 1);
        compute(buf);
        if ((iter & (KTILES - 1)) == KTILES - 1) {
            const int nb = (iter >> 5) << 7;
#pragma unroll
            for (int j = 0; j < 8; j++) {
                const int kk = nb + tx * 8 + j;
                const float cn = g_cnorm[kk];
#pragma unroll
                for (int i = 0; i < 8; i++) {
                    float s = fmaf(-2.f, acc[i][j], cn);
                    if (s < minv[i]) { minv[i] = s; mini[i] = kk; }
                }
            }
        }
        if (more) {
            stage(buf ^ 1);
            __syncthreads();
            buf ^= 1;
        }
    }

#pragma unroll
    for (int i = 0; i < 8; i++) {
        sval[ty * 8 + i][tx] = minv[i];
        sidx[ty * 8 + i][tx] = mini[i];
    }
    __syncthreads();
    if (tid < 128) {
        float bv = sval[tid][0];
        int   bi = sidx[tid][0];
#pragma unroll
        for (int x = 1; x < 16; x++) {
            float v = sval[tid][x];
            int   ii = sidx[tid][x];
            if (v < bv || (v == bv && ii < bi)) { bv = v; bi = ii; }
        }
        g_idx[rowBase + tid] = bi;
        if (idxOutF) idxOutF[rowBase + tid] = (float)bi;
    }
}

// ---------------- launch ---------------------------------------------------
extern "C" void kernel_launch(void* const* d_in, const int* in_sizes, int n_in,
                              void* d_out, int out_size) {
    const float* mels   = (const float*)d_in[0];
    const float* enc_w1 = (const float*)d_in[1];
    const float* enc_b1 = (const float*)d_in[2];
    const float* enc_w2 = (const float*)d_in[3];
    const float* enc_b2 = (const float*)d_in[4];
    const float* cb     = (const float*)d_in[5];
    const float* dec_w1 = (const float*)d_in[6];
    const float* dec_b1 = (const float*)d_in[7];
    const float* dec_w2 = (const float*)d_in[8];
    const float* dec_b2 = (const float*)d_in[9];

    float *bufA, *bufB;
    __nv_bfloat16 *whi, *wlo, *weh, *wem, *wel;
    cudaGetSymbolAddress((void**)&bufA, g_bufA);
    cudaGetSymbolAddress((void**)&bufB, g_bufB);
    cudaGetSymbolAddress((void**)&whi,  g_whi);
    cudaGetSymbolAddress((void**)&wlo,  g_wlo);
    cudaGetSymbolAddress((void**)&weh,  g_weh);
    cudaGetSymbolAddress((void**)&wem,  g_wem);
    cudaGetSymbolAddress((void**)&wel,  g_wel);

    float* out = (float*)d_out;
    float* idxOutF = (out_size >= RR * INC + RR) ? (out + (size_t)RR * INC) : nullptr;

    // prep
    k_wprep3<<<256, 256>>>(enc_w1, weh + WE_E1, wem + WE_E1, wel + WE_E1, INC, HC, 96, 512);
    k_wprep3<<<512, 256>>>(enc_w2, weh + WE_E2, wem + WE_E2, wel + WE_E2, HC, DC, 512, 512);
    k_wprep<<<512, 256>>>(dec_w1, whi + WO_D1, wlo + WO_D1, DC, HC, 512, 512);
    k_wprep<<<256, 256>>>(dec_w2, whi + WO_D2, wlo + WO_D2, HC, INC, 512, 128);
    k_cbT<<<512, 256>>>(cb);
    k_cnorm<<<KC, 256>>>(cb);

    constexpr int SMEM2 = 4 * (128 * 40 * 2) + 4 * (32 * 136 * 2);  // 75776 B
    constexpr int SMEM3 = 6 * (128 * 40 * 2) + 6 * (32 * 136 * 2);  // 113664 B

    cudaFuncSetAttribute((const void*)k_conv_mma3<INC, 96, 512, HC, true>,
                         cudaFuncAttributeMaxDynamicSharedMemorySize, SMEM3);
    cudaFuncSetAttribute((const void*)k_conv_mma3<HC, 512, 512, DC, false>,
                         cudaFuncAttributeMaxDynamicSharedMemorySize, SMEM3);
    cudaFuncSetAttribute((const void*)k_conv_mma<DC, 512, 512, HC, true, true>,
                         cudaFuncAttributeMaxDynamicSharedMemorySize, SMEM2);
    cudaFuncSetAttribute((const void*)k_conv_mma<HC, 512, 128, INC, false, false>,
                         cudaFuncAttributeMaxDynamicSharedMemorySize, SMEM2);

    // encoder: 3-term bf16 split on tensor cores (fp32-class accuracy)
    k_conv_mma3<INC, 96, 512, HC, true>
        <<<dim3(4, RR / 128), 256, SMEM3>>>(mels, weh + WE_E1, wem + WE_E1,
                                            wel + WE_E1, enc_b1, bufA);
    k_conv_mma3<HC, 512, 512, DC, false>
        <<<dim3(4, RR / 128), 256, SMEM3>>>(bufA, weh + WE_E2, wem + WE_E2,
                                            wel + WE_E2, enc_b2, bufB);

    // VQ (exact fp32) -> g_idx
    k_vq<<<RR / 128, 256>>>(bufB, idxOutF);

    // decoder via 2-term bf16 split (smooth error only)
    k_conv_mma<DC, 512, 512, HC, true, true>
        <<<dim3(4, RR / 128), 256, SMEM2>>>(cb, whi + WO_D1, wlo + WO_D1, dec_b1, bufA);
    k_conv_mma<HC, 512, 128, INC, false, false>
        <<<dim3(1, RR / 128), 256, SMEM2>>>(bufA, whi + WO_D2, wlo + WO_D2, dec_b2, out);
}

// round 9
// speedup vs baseline: 2.1092x; 1.1038x over previous
#include <cuda_runtime.h>
#include <cuda_bf16.h>
#include <math_constants.h>
#include <cstdint>

// ---------------- problem constants ----------------
#define BB   16
#define TT   2048
#define INC  80
#define HC   512
#define DC   512
#define KC   1024
#define RR   (BB*TT)          // 32768 rows

// ---------------- scratch ----------------
__device__ float g_bufA[(size_t)RR * DC];
__device__ __align__(16) __nv_bfloat16 g_whi[983040];  // dec weights hi
__device__ __align__(16) __nv_bfloat16 g_wlo[983040];  // dec weights lo
__device__ __align__(16) __nv_bfloat16 g_weh[933888];  // enc weights h
__device__ __align__(16) __nv_bfloat16 g_wem[933888];  // enc weights m
__device__ __align__(16) __nv_bfloat16 g_wel[933888];  // enc weights l
__device__ __align__(16) __nv_bfloat16 g_zh[(size_t)RR * DC];  // z split h
__device__ __align__(16) __nv_bfloat16 g_zm[(size_t)RR * DC];  // z split m
__device__ __align__(16) __nv_bfloat16 g_zl[(size_t)RR * DC];  // z split l
__device__ __align__(16) __nv_bfloat16 g_cbh[DC * KC]; // codebook split [D][K]
__device__ __align__(16) __nv_bfloat16 g_cbm[DC * KC];
__device__ __align__(16) __nv_bfloat16 g_cbl[DC * KC];
__device__ float g_cnorm[KC];
__device__ int   g_idx[RR];

// bf16 weight regions, layout [KPAD][COUTP]
#define WO_D1 0               // dec1: [1536][512]
#define WO_D2 786432          // dec2: [1536][128]
#define WE_E1 0               // enc1: [288][512]
#define WE_E2 147456          // enc2: [1536][512]

// ---------------- PTX helpers ---------------------------------------------
__device__ __forceinline__ uint32_t smem_u32(const void* p) {
    uint32_t a;
    asm("{ .reg .u64 t; cvta.to.shared.u64 t, %1; cvt.u32.u64 %0, t; }"
        : "=r"(a) : "l"(p));
    return a;
}
__device__ __forceinline__ void ldsm_x4(uint32_t* r, uint32_t addr) {
    asm volatile("ldmatrix.sync.aligned.m8n8.x4.shared.b16 {%0,%1,%2,%3}, [%4];"
                 : "=r"(r[0]), "=r"(r[1]), "=r"(r[2]), "=r"(r[3]) : "r"(addr));
}
__device__ __forceinline__ void ldsm_x4t(uint32_t* r, uint32_t addr) {
    asm volatile("ldmatrix.sync.aligned.m8n8.x4.trans.shared.b16 {%0,%1,%2,%3}, [%4];"
                 : "=r"(r[0]), "=r"(r[1]), "=r"(r[2]), "=r"(r[3]) : "r"(addr));
}
__device__ __forceinline__ void mma16816(float* c, const uint32_t* a,
                                         const uint32_t* b) {
    asm volatile(
        "mma.sync.aligned.m16n8k16.row.col.f32.bf16.bf16.f32 "
        "{%0,%1,%2,%3}, {%4,%5,%6,%7}, {%8,%9}, {%0,%1,%2,%3};"
        : "+f"(c[0]), "+f"(c[1]), "+f"(c[2]), "+f"(c[3])
        : "r"(a[0]), "r"(a[1]), "r"(a[2]), "r"(a[3]), "r"(b[0]), "r"(b[1]));
}
#define STS128(a, r0, r1, r2, r3) \
    asm volatile("st.shared.v4.b32 [%0], {%1,%2,%3,%4};" \
                 :: "r"(a), "r"(r0), "r"(r1), "r"(r2), "r"(r3) : "memory")

__device__ __forceinline__ uint32_t pack2bf(float a, float b) {
    __nv_bfloat162 h = __floats2bfloat162_rn(a, b);
    return *reinterpret_cast<uint32_t*>(&h);
}

// ---------------- prep kernels --------------------------------------------
__global__ void k_wprep(const float* __restrict__ w, __nv_bfloat16* __restrict__ hi,
                        __nv_bfloat16* __restrict__ lo,
                        int Cin, int Cout, int CinP, int CoutP) {
    int kpad = 3 * CinP;
    int n = kpad * CoutP;
    for (int i = blockIdx.x * blockDim.x + threadIdx.x; i < n;
         i += gridDim.x * blockDim.x) {
        int kp = i / CoutP;
        int nn = i - kp * CoutP;
        int dt = kp / CinP;
        int ci = kp - dt * CinP;
        float v = (nn < Cout && ci < Cin) ? w[(nn * Cin + ci) * 3 + dt] : 0.f;
        __nv_bfloat16 h = __float2bfloat16_rn(v);
        hi[i] = h;
        lo[i] = __float2bfloat16_rn(v - __bfloat162float(h));
    }
}
__global__ void k_wprep3(const float* __restrict__ w, __nv_bfloat16* __restrict__ wh,
                         __nv_bfloat16* __restrict__ wm, __nv_bfloat16* __restrict__ wl,
                         int Cin, int Cout, int CinP, int CoutP) {
    int kpad = 3 * CinP;
    int n = kpad * CoutP;
    for (int i = blockIdx.x * blockDim.x + threadIdx.x; i < n;
         i += gridDim.x * blockDim.x) {
        int kp = i / CoutP;
        int nn = i - kp * CoutP;
        int dt = kp / CinP;
        int ci = kp - dt * CinP;
        float v = (nn < Cout && ci < Cin) ? w[(nn * Cin + ci) * 3 + dt] : 0.f;
        __nv_bfloat16 h = __float2bfloat16_rn(v);
        float r = v - __bfloat162float(h);
        __nv_bfloat16 m = __float2bfloat16_rn(r);
        wh[i] = h;
        wm[i] = m;
        wl[i] = __float2bfloat16_rn(r - __bfloat162float(m));
    }
}
// codebook: cb[K][D] -> 3-term split [D][K]
__global__ void k_cbsplit(const float* __restrict__ cb) {
    int n = DC * KC;
    for (int i = blockIdx.x * blockDim.x + threadIdx.x; i < n;
         i += gridDim.x * blockDim.x) {
        int d = i >> 10;
        int k = i & (KC - 1);
        float v = cb[k * DC + d];
        __nv_bfloat16 h = __float2bfloat16_rn(v);
        float r = v - __bfloat162float(h);
        __nv_bfloat16 m = __float2bfloat16_rn(r);
        g_cbh[i] = h;
        g_cbm[i] = m;
        g_cbl[i] = __float2bfloat16_rn(r - __bfloat162float(m));
    }
}
__global__ void k_cnorm(const float* __restrict__ cb) {
    int k = blockIdx.x;
    float s = 0.f;
    for (int d = threadIdx.x; d < DC; d += 256) {
        float v = cb[k * DC + d];
        s += v * v;
    }
    __shared__ float red[256];
    red[threadIdx.x] = s;
    __syncthreads();
    for (int o = 128; o > 0; o >>= 1) {
        if (threadIdx.x < o) red[threadIdx.x] += red[threadIdx.x + o];
        __syncthreads();
    }
    if (threadIdx.x == 0) g_cnorm[k] = red[0];
}

// ---------------- conv GEMM via mma.sync, 2-term bf16 split (decoder) ------
template<int CIN, int CINP, int COUTP, int COUT, bool RELU, bool GATHER>
__global__ __launch_bounds__(256, 1)
void k_conv_mma(const float* __restrict__ A, const __nv_bfloat16* __restrict__ Whi,
                const __nv_bfloat16* __restrict__ Wlo, const float* __restrict__ bias,
                float* __restrict__ C) {
    constexpr int KPAD = 3 * CINP;
    constexpr int NCHUNK = KPAD / 32;
    constexpr int APITCH = 40;
    constexpr int BPITCH = 136;
    constexpr int ASZ = 128 * APITCH * 2;
    constexpr int BSZ = 32 * BPITCH * 2;

    extern __shared__ __align__(16) char smem[];
    const uint32_t sb = smem_u32(smem);
    const uint32_t oAH = sb, oAL = sb + 2 * ASZ;
    const uint32_t oBH = sb + 4 * ASZ, oBL = sb + 4 * ASZ + 2 * BSZ;

    const int tid = threadIdx.x;
    const int wid = tid >> 5, lane = tid & 31;
    const int mwarp = wid >> 2, nwarp = wid & 3;
    const int rowBase = blockIdx.y * 128;
    const int colBase = blockIdx.x * 128;

    const int ar = tid >> 1, half = tid & 1;
    const int r = rowBase + ar;
    const int tloc = r & (TT - 1);
    int gi[3];
    if (GATHER) {
#pragma unroll
        for (int dt = 0; dt < 3; dt++) {
            int rr = r + dt - 1;
            rr = rr < 0 ? 0 : (rr >= RR ? RR - 1 : rr);
            gi[dt] = g_idx[rr];
        }
    }
    const int bk = tid >> 3, seg = tid & 7;

    float4 va[4];
    uint4  wh[2], wl[2];

    auto fetch = [&](int c) {
        const int dt = (c * 32) / CINP;
        const int ci0 = c * 32 - dt * CINP;
        const bool ztap = (dt == 0 && tloc == 0) || (dt == 2 && tloc == TT - 1);
        const float* src;
        if (GATHER) {
            src = A + (size_t)gi[dt] * CIN;
        } else {
            src = A + (size_t)(r + dt - 1) * CIN;
        }
#pragma unroll
        for (int j = 0; j < 4; j++) {
            const int ci = ci0 + half * 16 + j * 4;
            const bool ok = !ztap && (CIN == CINP || ci < CIN);
            va[j] = ok ? *(const float4*)(src + ci) : make_float4(0.f, 0.f, 0.f, 0.f);
        }
        const size_t g = (size_t)(c * 32 + bk) * COUTP + colBase + seg * 16;
        wh[0] = *(const uint4*)(Whi + g);
        wh[1] = *(const uint4*)(Whi + g + 8);
        wl[0] = *(const uint4*)(Wlo + g);
        wl[1] = *(const uint4*)(Wlo + g + 8);
    };

    auto stage = [&](int buf) {
        float e[16];
        *(float4*)(e)      = va[0]; *(float4*)(e + 4)  = va[1];
        *(float4*)(e + 8)  = va[2]; *(float4*)(e + 12) = va[3];
        uint32_t hp[8], lp[8];
#pragma unroll
        for (int q = 0; q < 8; q++) {
            float h0 = __bfloat162float(__float2bfloat16_rn(e[2 * q]));
            float h1 = __bfloat162float(__float2bfloat16_rn(e[2 * q + 1]));
            hp[q] = pack2bf(h0, h1);
            lp[q] = pack2bf(e[2 * q] - h0, e[2 * q + 1] - h1);
        }
        const uint32_t aoff = (uint32_t)(ar * APITCH + half * 16) * 2 + buf * ASZ;
        STS128(oAH + aoff,      hp[0], hp[1], hp[2], hp[3]);
        STS128(oAH + aoff + 16, hp[4], hp[5], hp[6], hp[7]);
        STS128(oAL + aoff,      lp[0], lp[1], lp[2], lp[3]);
        STS128(oAL + aoff + 16, lp[4], lp[5], lp[6], lp[7]);
        const uint32_t boff = (uint32_t)(bk * BPITCH + seg * 16) * 2 + buf * BSZ;
        STS128(oBH + boff,      wh[0].x, wh[0].y, wh[0].z, wh[0].w);
        STS128(oBH + boff + 16, wh[1].x, wh[1].y, wh[1].z, wh[1].w);
        STS128(oBL + boff,      wl[0].x, wl[0].y, wl[0].z, wl[0].w);
        STS128(oBL + boff + 16, wl[1].x, wl[1].y, wl[1].z, wl[1].w);
    };

    float acc[4][4][4] = {};

    const uint32_t a_row = (lane & 15);
    const uint32_t a_k8  = (lane >> 4) * 8;
    const uint32_t b_k   = (lane & 15);
    const uint32_t b_n8  = (lane >> 4) * 8;

    auto compute = [&](int buf) {
        const uint32_t aH = oAH + buf * ASZ, aL = oAL + buf * ASZ;
        const uint32_t bH = oBH + buf * BSZ, bL = oBL + buf * BSZ;
#pragma unroll
        for (int ks = 0; ks < 2; ks++) {
            uint32_t AH[4][4], AL[4][4], BH[2][4], BL[2][4];
#pragma unroll
            for (int mt = 0; mt < 4; mt++) {
                const uint32_t ao =
                    ((mwarp * 64 + mt * 16 + a_row) * APITCH + ks * 16 + a_k8) * 2;
                ldsm_x4(AH[mt], aH + ao);
                ldsm_x4(AL[mt], aL + ao);
            }
#pragma unroll
            for (int pr = 0; pr < 2; pr++) {
                const uint32_t bo =
                    ((b_k + ks * 16) * BPITCH + nwarp * 32 + pr * 16 + b_n8) * 2;
                ldsm_x4t(BH[pr], bH + bo);
                ldsm_x4t(BL[pr], bL + bo);
            }
#pragma unroll
            for (int mt = 0; mt < 4; mt++)
#pragma unroll
                for (int nt = 0; nt < 4; nt++) {
                    const int pr = nt >> 1, hf = nt & 1;
                    mma16816(acc[mt][nt], AH[mt], &BH[pr][hf * 2]);
                    mma16816(acc[mt][nt], AL[mt], &BH[pr][hf * 2]);
                    mma16816(acc[mt][nt], AH[mt], &BL[pr][hf * 2]);
                }
        }
    };

    fetch(0);
    stage(0);
    __syncthreads();
    int buf = 0;
    for (int c = 1; c < NCHUNK; c++) {
        fetch(c);
        compute(buf);
        stage(buf ^ 1);
        __syncthreads();
        buf ^= 1;
    }
    compute(buf);

#pragma unroll
    for (int mt = 0; mt < 4; mt++) {
#pragma unroll
        for (int nt = 0; nt < 4; nt++) {
            const int col = colBase + nwarp * 32 + nt * 8 + (lane & 3) * 2;
            if ((COUT % 128) != 0 && col >= COUT) continue;
            const float b0 = bias[col], b1 = bias[col + 1];
            const int r0 = rowBase + mwarp * 64 + mt * 16 + (lane >> 2);
#pragma unroll
            for (int hh = 0; hh < 2; hh++) {
                float2 o;
                o.x = acc[mt][nt][hh * 2 + 0] + b0;
                o.y = acc[mt][nt][hh * 2 + 1] + b1;
                if (RELU) { o.x = fmaxf(o.x, 0.f); o.y = fmaxf(o.y, 0.f); }
                *(float2*)(C + (size_t)(r0 + hh * 8) * COUT + col) = o;
            }
        }
    }
}

// ---------------- conv GEMM via mma.sync, 3-term bf16 split (encoder) ------
// SPLITOUT: write output as 3-term bf16 split to g_zh/g_zm/g_zl (for VQ).
template<int CIN, int CINP, int COUTP, int COUT, bool RELU, bool SPLITOUT>
__global__ __launch_bounds__(256, 1)
void k_conv_mma3(const float* __restrict__ A, const __nv_bfloat16* __restrict__ Wh,
                 const __nv_bfloat16* __restrict__ Wm, const __nv_bfloat16* __restrict__ Wl,
                 const float* __restrict__ bias, float* __restrict__ C) {
    constexpr int KPAD = 3 * CINP;
    constexpr int NCHUNK = KPAD / 32;
    constexpr int APITCH = 40;
    constexpr int BPITCH = 136;
    constexpr int ASZ = 128 * APITCH * 2;
    constexpr int BSZ = 32 * BPITCH * 2;

    extern __shared__ __align__(16) char smem[];
    const uint32_t sb = smem_u32(smem);
    const uint32_t oAH = sb, oAM = sb + 2 * ASZ, oAL = sb + 4 * ASZ;
    const uint32_t oBH = sb + 6 * ASZ, oBM = oBH + 2 * BSZ, oBL = oBH + 4 * BSZ;

    const int tid = threadIdx.x;
    const int wid = tid >> 5, lane = tid & 31;
    const int mwarp = wid >> 2, nwarp = wid & 3;
    const int rowBase = blockIdx.y * 128;
    const int colBase = blockIdx.x * 128;

    const int ar = tid >> 1, half = tid & 1;
    const int r = rowBase + ar;
    const int tloc = r & (TT - 1);
    const int bk = tid >> 3, seg = tid & 7;

    float4 va[4];
    uint4  wwh[2], wwm[2], wwl[2];

    auto fetch = [&](int c) {
        const int dt = (c * 32) / CINP;
        const int ci0 = c * 32 - dt * CINP;
        const bool ztap = (dt == 0 && tloc == 0) || (dt == 2 && tloc == TT - 1);
        const float* src = A + (size_t)(r + dt - 1) * CIN;
#pragma unroll
        for (int j = 0; j < 4; j++) {
            const int ci = ci0 + half * 16 + j * 4;
            const bool ok = !ztap && (CIN == CINP || ci < CIN);
            va[j] = ok ? *(const float4*)(src + ci) : make_float4(0.f, 0.f, 0.f, 0.f);
        }
        const size_t g = (size_t)(c * 32 + bk) * COUTP + colBase + seg * 16;
        wwh[0] = *(const uint4*)(Wh + g);  wwh[1] = *(const uint4*)(Wh + g + 8);
        wwm[0] = *(const uint4*)(Wm + g);  wwm[1] = *(const uint4*)(Wm + g + 8);
        wwl[0] = *(const uint4*)(Wl + g);  wwl[1] = *(const uint4*)(Wl + g + 8);
    };

    auto stage = [&](int buf) {
        float e[16];
        *(float4*)(e)      = va[0]; *(float4*)(e + 4)  = va[1];
        *(float4*)(e + 8)  = va[2]; *(float4*)(e + 12) = va[3];
        uint32_t hp[8], mp[8], lp[8];
#pragma unroll
        for (int q = 0; q < 8; q++) {
            float x0 = e[2 * q], x1 = e[2 * q + 1];
            float h0 = __bfloat162float(__float2bfloat16_rn(x0));
            float h1 = __bfloat162float(__float2bfloat16_rn(x1));
            float r0 = x0 - h0, r1 = x1 - h1;
            float m0 = __bfloat162float(__float2bfloat16_rn(r0));
            float m1 = __bfloat162float(__float2bfloat16_rn(r1));
            hp[q] = pack2bf(h0, h1);
            mp[q] = pack2bf(m0, m1);
            lp[q] = pack2bf(r0 - m0, r1 - m1);
        }
        const uint32_t aoff = (uint32_t)(ar * APITCH + half * 16) * 2 + buf * ASZ;
        STS128(oAH + aoff,      hp[0], hp[1], hp[2], hp[3]);
        STS128(oAH + aoff + 16, hp[4], hp[5], hp[6], hp[7]);
        STS128(oAM + aoff,      mp[0], mp[1], mp[2], mp[3]);
        STS128(oAM + aoff + 16, mp[4], mp[5], mp[6], mp[7]);
        STS128(oAL + aoff,      lp[0], lp[1], lp[2], lp[3]);
        STS128(oAL + aoff + 16, lp[4], lp[5], lp[6], lp[7]);
        const uint32_t boff = (uint32_t)(bk * BPITCH + seg * 16) * 2 + buf * BSZ;
        STS128(oBH + boff,      wwh[0].x, wwh[0].y, wwh[0].z, wwh[0].w);
        STS128(oBH + boff + 16, wwh[1].x, wwh[1].y, wwh[1].z, wwh[1].w);
        STS128(oBM + boff,      wwm[0].x, wwm[0].y, wwm[0].z, wwm[0].w);
        STS128(oBM + boff + 16, wwm[1].x, wwm[1].y, wwm[1].z, wwm[1].w);
        STS128(oBL + boff,      wwl[0].x, wwl[0].y, wwl[0].z, wwl[0].w);
        STS128(oBL + boff + 16, wwl[1].x, wwl[1].y, wwl[1].z, wwl[1].w);
    };

    float acc[4][4][4] = {};

    const uint32_t a_row = (lane & 15);
    const uint32_t a_k8  = (lane >> 4) * 8;
    const uint32_t b_k   = (lane & 15);
    const uint32_t b_n8  = (lane >> 4) * 8;

    auto compute = [&](int buf) {
        const uint32_t aH = oAH + buf * ASZ, aM = oAM + buf * ASZ, aL = oAL + buf * ASZ;
        const uint32_t bH = oBH + buf * BSZ, bM = oBM + buf * BSZ, bL = oBL + buf * BSZ;
#pragma unroll
        for (int ks = 0; ks < 2; ks++) {
            uint32_t AH[4][4], AM[4][4], AL[4][4];
            uint32_t BH[2][4], BM[2][4], BL[2][4];
#pragma unroll
            for (int mt = 0; mt < 4; mt++) {
                const uint32_t ao =
                    ((mwarp * 64 + mt * 16 + a_row) * APITCH + ks * 16 + a_k8) * 2;
                ldsm_x4(AH[mt], aH + ao);
                ldsm_x4(AM[mt], aM + ao);
                ldsm_x4(AL[mt], aL + ao);
            }
#pragma unroll
            for (int pr = 0; pr < 2; pr++) {
                const uint32_t bo =
                    ((b_k + ks * 16) * BPITCH + nwarp * 32 + pr * 16 + b_n8) * 2;
                ldsm_x4t(BH[pr], bH + bo);
                ldsm_x4t(BM[pr], bM + bo);
                ldsm_x4t(BL[pr], bL + bo);
            }
#pragma unroll
            for (int mt = 0; mt < 4; mt++)
#pragma unroll
                for (int nt = 0; nt < 4; nt++) {
                    const int pr = nt >> 1, hf = nt & 1;
                    float* a = acc[mt][nt];
                    mma16816(a, AH[mt], &BH[pr][hf * 2]);
                    mma16816(a, AH[mt], &BM[pr][hf * 2]);
                    mma16816(a, AM[mt], &BH[pr][hf * 2]);
                    mma16816(a, AH[mt], &BL[pr][hf * 2]);
                    mma16816(a, AM[mt], &BM[pr][hf * 2]);
                    mma16816(a, AL[mt], &BH[pr][hf * 2]);
                }
        }
    };

    fetch(0);
    stage(0);
    __syncthreads();
    int buf = 0;
    for (int c = 1; c < NCHUNK; c++) {
        fetch(c);
        compute(buf);
        stage(buf ^ 1);
        __syncthreads();
        buf ^= 1;
    }
    compute(buf);

#pragma unroll
    for (int mt = 0; mt < 4; mt++) {
#pragma unroll
        for (int nt = 0; nt < 4; nt++) {
            const int col = colBase + nwarp * 32 + nt * 8 + (lane & 3) * 2;
            if ((COUT % 128) != 0 && col >= COUT) continue;
            const float b0 = bias[col], b1 = bias[col + 1];
            const int r0 = rowBase + mwarp * 64 + mt * 16 + (lane >> 2);
#pragma unroll
            for (int hh = 0; hh < 2; hh++) {
                float ox = acc[mt][nt][hh * 2 + 0] + b0;
                float oy = acc[mt][nt][hh * 2 + 1] + b1;
                if (RELU) { ox = fmaxf(ox, 0.f); oy = fmaxf(oy, 0.f); }
                if (SPLITOUT) {
                    const size_t base = (size_t)(r0 + hh * 8) * COUT + col;
                    float hx = __bfloat162float(__float2bfloat16_rn(ox));
                    float hy = __bfloat162float(__float2bfloat16_rn(oy));
                    float rx = ox - hx, ry = oy - hy;
                    float mx = __bfloat162float(__float2bfloat16_rn(rx));
                    float my = __bfloat162float(__float2bfloat16_rn(ry));
                    *(uint32_t*)(g_zh + base) = pack2bf(hx, hy);
                    *(uint32_t*)(g_zm + base) = pack2bf(mx, my);
                    *(uint32_t*)(g_zl + base) = pack2bf(rx - mx, ry - my);
                } else {
                    float2 o = make_float2(ox, oy);
                    *(float2*)(C + (size_t)(r0 + hh * 8) * COUT + col) = o;
                }
            }
        }
    }
}

// ---------------- VQ via mma.sync 3-term split + fused argmin --------------
// scores[r][k] = cnorm[k] - 2 * dot(z[r], cb[k]);  idx = argmin_k (first min)
__global__ __launch_bounds__(256, 1)
void k_vq_mma(float* __restrict__ idxOutF) {
    constexpr int APITCH = 40;
    constexpr int BPITCH = 136;
    constexpr int ASZ = 128 * APITCH * 2;
    constexpr int BSZ = 32 * BPITCH * 2;
    constexpr int NITER = (KC / 128) * (DC / 32);   // 8 * 16 = 128

    extern __shared__ __align__(16) char smem[];
    const uint32_t sb = smem_u32(smem);
    const uint32_t oAH = sb, oAM = sb + 2 * ASZ, oAL = sb + 4 * ASZ;
    const uint32_t oBH = sb + 6 * ASZ, oBM = oBH + 2 * BSZ, oBL = oBH + 4 * BSZ;

    const int tid = threadIdx.x;
    const int wid = tid >> 5, lane = tid & 31;
    const int mwarp = wid >> 2, nwarp = wid & 3;
    const int rowBase = blockIdx.x * 128;

    const int ar = tid >> 1, half = tid & 1;
    const size_t zrow = (size_t)(rowBase + ar) * DC + half * 16;
    const int bk = tid >> 3, seg = tid & 7;

    uint4 zah[2], zam[2], zal[2], wbh[2], wbm[2], wbl[2];

    auto fetch = [&](int it) {
        const int nb = it >> 4;
        const int d0 = (it & 15) << 5;
        zah[0] = *(const uint4*)(g_zh + zrow + d0);
        zah[1] = *(const uint4*)(g_zh + zrow + d0 + 8);
        zam[0] = *(const uint4*)(g_zm + zrow + d0);
        zam[1] = *(const uint4*)(g_zm + zrow + d0 + 8);
        zal[0] = *(const uint4*)(g_zl + zrow + d0);
        zal[1] = *(const uint4*)(g_zl + zrow + d0 + 8);
        const size_t g = (size_t)(d0 + bk) * KC + (nb << 7) + seg * 16;
        wbh[0] = *(const uint4*)(g_cbh + g);  wbh[1] = *(const uint4*)(g_cbh + g + 8);
        wbm[0] = *(const uint4*)(g_cbm + g);  wbm[1] = *(const uint4*)(g_cbm + g + 8);
        wbl[0] = *(const uint4*)(g_cbl + g);  wbl[1] = *(const uint4*)(g_cbl + g + 8);
    };

    auto stage = [&](int buf) {
        const uint32_t aoff = (uint32_t)(ar * APITCH + half * 16) * 2 + buf * ASZ;
        STS128(oAH + aoff,      zah[0].x, zah[0].y, zah[0].z, zah[0].w);
        STS128(oAH + aoff + 16, zah[1].x, zah[1].y, zah[1].z, zah[1].w);
        STS128(oAM + aoff,      zam[0].x, zam[0].y, zam[0].z, zam[0].w);
        STS128(oAM + aoff + 16, zam[1].x, zam[1].y, zam[1].z, zam[1].w);
        STS128(oAL + aoff,      zal[0].x, zal[0].y, zal[0].z, zal[0].w);
        STS128(oAL + aoff + 16, zal[1].x, zal[1].y, zal[1].z, zal[1].w);
        const uint32_t boff = (uint32_t)(bk * BPITCH + seg * 16) * 2 + buf * BSZ;
        STS128(oBH + boff,      wbh[0].x, wbh[0].y, wbh[0].z, wbh[0].w);
        STS128(oBH + boff + 16, wbh[1].x, wbh[1].y, wbh[1].z, wbh[1].w);
        STS128(oBM + boff,      wbm[0].x, wbm[0].y, wbm[0].z, wbm[0].w);
        STS128(oBM + boff + 16, wbm[1].x, wbm[1].y, wbm[1].z, wbm[1].w);
        STS128(oBL + boff,      wbl[0].x, wbl[0].y, wbl[0].z, wbl[0].w);
        STS128(oBL + boff + 16, wbl[1].x, wbl[1].y, wbl[1].z, wbl[1].w);
    };

    float acc[4][4][4];
    float minv[4][2];
    int   mini[4][2];
#pragma unroll
    for (int mt = 0; mt < 4; mt++)
#pragma unroll
        for (int hh = 0; hh < 2; hh++) { minv[mt][hh] = CUDART_INF_F; mini[mt][hh] = 0; }

    const uint32_t a_row = (lane & 15);
    const uint32_t a_k8  = (lane >> 4) * 8;
    const uint32_t b_k   = (lane & 15);
    const uint32_t b_n8  = (lane >> 4) * 8;

    auto compute = [&](int buf) {
        const uint32_t aH = oAH + buf * ASZ, aM = oAM + buf * ASZ, aL = oAL + buf * ASZ;
        const uint32_t bH = oBH + buf * BSZ, bM = oBM + buf * BSZ, bL = oBL + buf * BSZ;
#pragma unroll
        for (int ks = 0; ks < 2; ks++) {
            uint32_t AH[4][4], AM[4][4], AL[4][4];
            uint32_t BH[2][4], BM[2][4], BL[2][4];
#pragma unroll
            for (int mt = 0; mt < 4; mt++) {
                const uint32_t ao =
                    ((mwarp * 64 + mt * 16 + a_row) * APITCH + ks * 16 + a_k8) * 2;
                ldsm_x4(AH[mt], aH + ao);
                ldsm_x4(AM[mt], aM + ao);
                ldsm_x4(AL[mt], aL + ao);
            }
#pragma unroll
            for (int pr = 0; pr < 2; pr++) {
                const uint32_t bo =
                    ((b_k + ks * 16) * BPITCH + nwarp * 32 + pr * 16 + b_n8) * 2;
                ldsm_x4t(BH[pr], bH + bo);
                ldsm_x4t(BM[pr], bM + bo);
                ldsm_x4t(BL[pr], bL + bo);
            }
#pragma unroll
            for (int mt = 0; mt < 4; mt++)
#pragma unroll
                for (int nt = 0; nt < 4; nt++) {
                    const int pr = nt >> 1, hf = nt & 1;
                    float* a = acc[mt][nt];
                    mma16816(a, AH[mt], &BH[pr][hf * 2]);
                    mma16816(a, AH[mt], &BM[pr][hf * 2]);
                    mma16816(a, AM[mt], &BH[pr][hf * 2]);
                    mma16816(a, AH[mt], &BL[pr][hf * 2]);
                    mma16816(a, AM[mt], &BM[pr][hf * 2]);
                    mma16816(a, AL[mt], &BH[pr][hf * 2]);
                }
        }
    };

    fetch(0);
    stage(0);
    __syncthreads();
    int buf = 0;
    for (int it = 0; it < NITER; it++) {
        if ((it & 15) == 0) {
#pragma unroll
            for (int mt = 0; mt < 4; mt++)
#pragma unroll
                for (int nt = 0; nt < 4; nt++)
#pragma unroll
                    for (int q = 0; q < 4; q++) acc[mt][nt][q] = 0.f;
        }
        const bool more = (it + 1 < NITER);
        if (more) fetch(it + 1);
        compute(buf);
        if ((it & 15) == 15) {
            const int nb = it >> 4;
#pragma unroll
            for (int nt = 0; nt < 4; nt++) {
                const int kk = (nb << 7) + nwarp * 32 + nt * 8 + (lane & 3) * 2;
                const float cn0 = g_cnorm[kk];
                const float cn1 = g_cnorm[kk + 1];
#pragma unroll
                for (int mt = 0; mt < 4; mt++)
#pragma unroll
                    for (int hh = 0; hh < 2; hh++) {
                        const float s0 = fmaf(-2.f, acc[mt][nt][hh * 2 + 0], cn0);
                        const float s1 = fmaf(-2.f, acc[mt][nt][hh * 2 + 1], cn1);
                        if (s0 < minv[mt][hh]) { minv[mt][hh] = s0; mini[mt][hh] = kk; }
                        if (s1 < minv[mt][hh]) { minv[mt][hh] = s1; mini[mt][hh] = kk + 1; }
                    }
            }
        }
        if (more) {
            stage(buf ^ 1);
            __syncthreads();
            buf ^= 1;
        }
    }

    // final reduction: alias staging smem (no longer needed)
    __syncthreads();
    float (*sval)[17] = (float(*)[17])(smem);
    int   (*sidx)[17] = (int(*)[17])(smem + 128 * 17 * 4);
    const int contrib = nwarp * 4 + (lane & 3);
#pragma unroll
    for (int mt = 0; mt < 4; mt++)
#pragma unroll
        for (int hh = 0; hh < 2; hh++) {
            const int row = mwarp * 64 + mt * 16 + (lane >> 2) + hh * 8;
            sval[row][contrib] = minv[mt][hh];
            sidx[row][contrib] = mini[mt][hh];
        }
    __syncthreads();
    if (tid < 128) {
        float bv = sval[tid][0];
        int   bi = sidx[tid][0];
#pragma unroll
        for (int x = 1; x < 16; x++) {
            float v = sval[tid][x];
            int   ii = sidx[tid][x];
            if (v < bv || (v == bv && ii < bi)) { bv = v; bi = ii; }
        }
        g_idx[rowBase + tid] = bi;
        if (idxOutF) idxOutF[rowBase + tid] = (float)bi;
    }
}

// ---------------- launch ---------------------------------------------------
extern "C" void kernel_launch(void* const* d_in, const int* in_sizes, int n_in,
                              void* d_out, int out_size) {
    const float* mels   = (const float*)d_in[0];
    const float* enc_w1 = (const float*)d_in[1];
    const float* enc_b1 = (const float*)d_in[2];
    const float* enc_w2 = (const float*)d_in[3];
    const float* enc_b2 = (const float*)d_in[4];
    const float* cb     = (const float*)d_in[5];
    const float* dec_w1 = (const float*)d_in[6];
    const float* dec_b1 = (const float*)d_in[7];
    const float* dec_w2 = (const float*)d_in[8];
    const float* dec_b2 = (const float*)d_in[9];

    float *bufA;
    __nv_bfloat16 *whi, *wlo, *weh, *wem, *wel;
    cudaGetSymbolAddress((void**)&bufA, g_bufA);
    cudaGetSymbolAddress((void**)&whi,  g_whi);
    cudaGetSymbolAddress((void**)&wlo,  g_wlo);
    cudaGetSymbolAddress((void**)&weh,  g_weh);
    cudaGetSymbolAddress((void**)&wem,  g_wem);
    cudaGetSymbolAddress((void**)&wel,  g_wel);

    float* out = (float*)d_out;
    float* idxOutF = (out_size >= RR * INC + RR) ? (out + (size_t)RR * INC) : nullptr;

    // prep
    k_wprep3<<<256, 256>>>(enc_w1, weh + WE_E1, wem + WE_E1, wel + WE_E1, INC, HC, 96, 512);
    k_wprep3<<<512, 256>>>(enc_w2, weh + WE_E2, wem + WE_E2, wel + WE_E2, HC, DC, 512, 512);
    k_wprep<<<512, 256>>>(dec_w1, whi + WO_D1, wlo + WO_D1, DC, HC, 512, 512);
    k_wprep<<<256, 256>>>(dec_w2, whi + WO_D2, wlo + WO_D2, HC, INC, 512, 128);
    k_cbsplit<<<512, 256>>>(cb);
    k_cnorm<<<KC, 256>>>(cb);

    constexpr int SMEM2 = 4 * (128 * 40 * 2) + 4 * (32 * 136 * 2);  // 75776 B
    constexpr int SMEM3 = 6 * (128 * 40 * 2) + 6 * (32 * 136 * 2);  // 113664 B

    cudaFuncSetAttribute((const void*)k_conv_mma3<INC, 96, 512, HC, true, false>,
                         cudaFuncAttributeMaxDynamicSharedMemorySize, SMEM3);
    cudaFuncSetAttribute((const void*)k_conv_mma3<HC, 512, 512, DC, false, true>,
                         cudaFuncAttributeMaxDynamicSharedMemorySize, SMEM3);
    cudaFuncSetAttribute((const void*)k_vq_mma,
                         cudaFuncAttributeMaxDynamicSharedMemorySize, SMEM3);
    cudaFuncSetAttribute((const void*)k_conv_mma<DC, 512, 512, HC, true, true>,
                         cudaFuncAttributeMaxDynamicSharedMemorySize, SMEM2);
    cudaFuncSetAttribute((const void*)k_conv_mma<HC, 512, 128, INC, false, false>,
                         cudaFuncAttributeMaxDynamicSharedMemorySize, SMEM2);

    // encoder: 3-term bf16 split on tensor cores (fp32-class accuracy)
    k_conv_mma3<INC, 96, 512, HC, true, false>
        <<<dim3(4, RR / 128), 256, SMEM3>>>(mels, weh + WE_E1, wem + WE_E1,
                                            wel + WE_E1, enc_b1, bufA);
    // enc2 writes z directly as 3-term bf16 split (g_zh/g_zm/g_zl)
    k_conv_mma3<HC, 512, 512, DC, false, true>
        <<<dim3(4, RR / 128), 256, SMEM3>>>(bufA, weh + WE_E2, wem + WE_E2,
                                            wel + WE_E2, enc_b2, nullptr);

    // VQ on tensor cores (3-term split scores + fused argmin) -> g_idx
    k_vq_mma<<<RR / 128, 256, SMEM3>>>(idxOutF);

    // decoder via 2-term bf16 split (smooth error only)
    k_conv_mma<DC, 512, 512, HC, true, true>
        <<<dim3(4, RR / 128), 256, SMEM2>>>(cb, whi + WO_D1, wlo + WO_D1, dec_b1, bufA);
    k_conv_mma<HC, 512, 128, INC, false, false>
        <<<dim3(1, RR / 128), 256, SMEM2>>>(bufA, whi + WO_D2, wlo + WO_D2, dec_b2, out);
}